// round 4
// baseline (speedup 1.0000x reference)
#include <cuda_runtime.h>
#include <cstdint>

#define NNODES 30000
#define RREL   8
#define DIM    256           // IN_DIM == HID == 256 (per-relation row block)
#define KDIM   2304          // R*DIM + DIM (self/root block appended)
#define HIDD   256
#define ZDIM   128
#define NBASE  30

// ---- static device scratch (allocation-free rule) ----
__device__ float g_H[NNODES * KDIM];        // 276.5 MB  [N, 2304] GEMM A
__device__ float g_Z[NNODES * HIDD];        // 30.7 MB   layer-1 output
__device__ float g_cnt[NNODES * RREL];      // segment counts -> inverted
__device__ float g_W1[KDIM * HIDD];         // [2304, 256]
__device__ float g_W2[KDIM * ZDIM];         // [2304, 128]

// ---------------------------------------------------------------------------
// Build concatenated weight: rows [0,2048): W[r] = sum_b comp[r,b]*bases[b];
// rows [2048,2304): root.
// ---------------------------------------------------------------------------
template<int OUTD, bool W1SEL>
__global__ void build_w(const float* __restrict__ bases,
                        const float* __restrict__ comp,
                        const float* __restrict__ root)
{
    float* __restrict__ W = W1SEL ? g_W1 : g_W2;
    int idx = blockIdx.x * blockDim.x + threadIdx.x;
    if (idx >= KDIM * OUTD) return;
    int k = idx / OUTD;
    int o = idx - k * OUTD;
    if (k < RREL * DIM) {
        int r = k >> 8;
        int i = k & 255;
        float acc = 0.f;
        #pragma unroll
        for (int b = 0; b < NBASE; b++)
            acc += comp[r * NBASE + b] * bases[((size_t)b * DIM + i) * OUTD + o];
        W[idx] = acc;
    } else {
        W[idx] = root[(size_t)(k - RREL * DIM) * OUTD + o];
    }
}

// ---------------------------------------------------------------------------
// Segment counting / inversion.  Indices are INT32 (jax default, x64 disabled).
// ---------------------------------------------------------------------------
__global__ void zero_cnt_kernel()
{
    int i = blockIdx.x * blockDim.x + threadIdx.x;
    if (i < NNODES * RREL) g_cnt[i] = 0.f;
}

__global__ void count_edges(const int* __restrict__ ei,
                            const int* __restrict__ et, int E)
{
    int e = blockIdx.x * blockDim.x + threadIdx.x;
    if (e >= E) return;
    int dst = ei[E + e];
    int r   = et[e];
    if ((unsigned)dst >= NNODES || (unsigned)r >= RREL) return;  // diag guard
    atomicAdd(&g_cnt[dst * RREL + r], 1.0f);
}

__global__ void invert_cnt()
{
    int i = blockIdx.x * blockDim.x + threadIdx.x;
    if (i < NNODES * RREL) g_cnt[i] = 1.0f / fmaxf(g_cnt[i], 1.0f);
}

// ---------------------------------------------------------------------------
// Init H: zero the 8 relation blocks, copy self-features into tail block.
// ---------------------------------------------------------------------------
template<bool USE_GZ>
__global__ void init_H(const float* __restrict__ tail)
{
    const int per = KDIM / 4;            // 576 float4 per node
    int idx = blockIdx.x * blockDim.x + threadIdx.x;
    if (idx >= NNODES * per) return;
    int n = idx / per;
    int c = idx - n * per;
    float4 v;
    if (c < (RREL * DIM) / 4) {
        v = make_float4(0.f, 0.f, 0.f, 0.f);
    } else {
        const float4* t4 = USE_GZ ? (const float4*)g_Z : (const float4*)tail;
        v = t4[(size_t)n * (DIM / 4) + (c - (RREL * DIM) / 4)];
    }
    ((float4*)g_H)[idx] = v;
}

// ---------------------------------------------------------------------------
// Scatter: one warp per edge; H[dst, etype, :] += feat[src] * invcnt[dst,etype]
// Scalar f32 atomics (REDG.ADD.F32).
// ---------------------------------------------------------------------------
template<bool USE_GZ>
__global__ void scatter_edges(const int* __restrict__ ei,
                              const int* __restrict__ et,
                              const float* __restrict__ feat_in, int E)
{
    int gw   = (blockIdx.x * blockDim.x + threadIdx.x) >> 5;
    int lane = threadIdx.x & 31;
    if (gw >= E) return;
    const float* __restrict__ feat = USE_GZ ? g_Z : feat_in;
    int src = ei[gw];
    int dst = ei[E + gw];
    int r   = et[gw];
    if ((unsigned)src >= NNODES || (unsigned)dst >= NNODES ||
        (unsigned)r >= RREL) return;                       // diag guard
    float s = g_cnt[dst * RREL + r];     // already inverted
    const float4* xr = (const float4*)(feat + (size_t)src * DIM);
    float* hb = g_H + (size_t)dst * KDIM + r * DIM;
    #pragma unroll
    for (int i = 0; i < 2; i++) {
        int f = lane + 32 * i;
        float4 v = xr[f];
        float* p = hb + 4 * f;
        atomicAdd(p + 0, v.x * s);
        atomicAdd(p + 1, v.y * s);
        atomicAdd(p + 2, v.z * s);
        atomicAdd(p + 3, v.w * s);
    }
}

// ---------------------------------------------------------------------------
// fp32 GEMM: C[M, OUTD] = g_H[M, 2304] @ (g_W1|g_W2)[2304, OUTD] + bias, (leaky)
// 128x128x16 tiles, 256 threads, 8x8 per thread, register-prefetch pipeline.
// ---------------------------------------------------------------------------
template<int OUTD, bool RELU, bool TO_GZ>
__global__ void __launch_bounds__(256, 2)
gemm_k(const float* __restrict__ bias, float* __restrict__ Cout)
{
    const float* __restrict__ Bw = (OUTD == HIDD) ? g_W1 : g_W2;
    float* __restrict__ C = TO_GZ ? g_Z : Cout;
    const int M = NNODES, N = OUTD, K = KDIM;

    __shared__ float As[16][132];     // [k][m], padded stride
    __shared__ float Bs[16][128];     // [k][n]

    int tid = threadIdx.x;
    int tx = tid & 15, ty = tid >> 4;
    int bm = blockIdx.x * 128;
    int bn = blockIdx.y * 128;

    float acc[8][8];
    #pragma unroll
    for (int i = 0; i < 8; i++)
        #pragma unroll
        for (int j = 0; j < 8; j++) acc[i][j] = 0.f;

    int arow = tid >> 2;              // 0..63  (+64 for second)
    int acol = (tid & 3) * 4;         // k offset within tile
    int brow = tid >> 5;              // 0..7   (+8 for second)
    int bcol = (tid & 31) * 4;        // n offset

    const float* Abase = g_H + (size_t)bm * K;

    float4 ar[2], br[2];

    // prologue: load tile 0
    #pragma unroll
    for (int i = 0; i < 2; i++) {
        int row = arow + 64 * i;
        ar[i] = (bm + row < M)
              ? *(const float4*)(Abase + (size_t)row * K + acol)
              : make_float4(0.f, 0.f, 0.f, 0.f);
        br[i] = *(const float4*)(Bw + (size_t)(brow + 8 * i) * N + bn + bcol);
    }
    #pragma unroll
    for (int i = 0; i < 2; i++) {
        int row = arow + 64 * i;
        As[acol + 0][row] = ar[i].x;
        As[acol + 1][row] = ar[i].y;
        As[acol + 2][row] = ar[i].z;
        As[acol + 3][row] = ar[i].w;
        *(float4*)&Bs[brow + 8 * i][bcol] = br[i];
    }
    __syncthreads();

    for (int kt = 16; kt < KDIM; kt += 16) {
        // prefetch next tile into registers
        #pragma unroll
        for (int i = 0; i < 2; i++) {
            int row = arow + 64 * i;
            ar[i] = (bm + row < M)
                  ? *(const float4*)(Abase + (size_t)row * K + kt + acol)
                  : make_float4(0.f, 0.f, 0.f, 0.f);
            br[i] = *(const float4*)(Bw + (size_t)(kt + brow + 8 * i) * N + bn + bcol);
        }
        // compute on current smem tile
        #pragma unroll
        for (int k = 0; k < 16; k++) {
            float a[8], b[8];
            #pragma unroll
            for (int i = 0; i < 8; i++) a[i] = As[k][ty * 8 + i];
            float4 b0 = *(float4*)&Bs[k][tx * 8];
            float4 b1 = *(float4*)&Bs[k][tx * 8 + 4];
            b[0] = b0.x; b[1] = b0.y; b[2] = b0.z; b[3] = b0.w;
            b[4] = b1.x; b[5] = b1.y; b[6] = b1.z; b[7] = b1.w;
            #pragma unroll
            for (int i = 0; i < 8; i++)
                #pragma unroll
                for (int j = 0; j < 8; j++)
                    acc[i][j] = fmaf(a[i], b[j], acc[i][j]);
        }
        __syncthreads();
        #pragma unroll
        for (int i = 0; i < 2; i++) {
            int row = arow + 64 * i;
            As[acol + 0][row] = ar[i].x;
            As[acol + 1][row] = ar[i].y;
            As[acol + 2][row] = ar[i].z;
            As[acol + 3][row] = ar[i].w;
            *(float4*)&Bs[brow + 8 * i][bcol] = br[i];
        }
        __syncthreads();
    }
    // last tile
    #pragma unroll
    for (int k = 0; k < 16; k++) {
        float a[8], b[8];
        #pragma unroll
        for (int i = 0; i < 8; i++) a[i] = As[k][ty * 8 + i];
        float4 b0 = *(float4*)&Bs[k][tx * 8];
        float4 b1 = *(float4*)&Bs[k][tx * 8 + 4];
        b[0] = b0.x; b[1] = b0.y; b[2] = b0.z; b[3] = b0.w;
        b[4] = b1.x; b[5] = b1.y; b[6] = b1.z; b[7] = b1.w;
        #pragma unroll
        for (int i = 0; i < 8; i++)
            #pragma unroll
            for (int j = 0; j < 8; j++)
                acc[i][j] = fmaf(a[i], b[j], acc[i][j]);
    }

    // epilogue: bias + (leaky relu) + store
    float bv[8];
    #pragma unroll
    for (int j = 0; j < 8; j++) bv[j] = bias[bn + tx * 8 + j];
    #pragma unroll
    for (int i = 0; i < 8; i++) {
        int row = bm + ty * 8 + i;
        if (row < M) {
            #pragma unroll
            for (int j = 0; j < 8; j++) {
                float v = acc[i][j] + bv[j];
                if (RELU) v = (v > 0.f) ? v : 0.01f * v;
                C[(size_t)row * N + bn + tx * 8 + j] = v;
            }
        }
    }
}

// ---------------------------------------------------------------------------
extern "C" void kernel_launch(void* const* d_in, const int* in_sizes, int n_in,
                              void* d_out, int out_size)
{
    const float* x      = (const float*)d_in[0];
    const int*   ei     = (const int*)d_in[1];     // int32 (jax default int)
    const int*   et     = (const int*)d_in[2];     // int32
    const float* bases1 = (const float*)d_in[3];
    const float* comp1  = (const float*)d_in[4];
    const float* root1  = (const float*)d_in[5];
    const float* bias1  = (const float*)d_in[6];
    const float* bases2 = (const float*)d_in[7];
    const float* comp2  = (const float*)d_in[8];
    const float* root2  = (const float*)d_in[9];
    const float* bias2  = (const float*)d_in[10];
    float* out = (float*)d_out;
    int E = in_sizes[2];

    // weights (recomputed every call; tiny)
    build_w<HIDD, true ><<<(KDIM * HIDD + 255) / 256, 256>>>(bases1, comp1, root1);
    build_w<ZDIM, false><<<(KDIM * ZDIM + 255) / 256, 256>>>(bases2, comp2, root2);

    // segment counts (shared by both layers)
    zero_cnt_kernel<<<(NNODES * RREL + 255) / 256, 256>>>();
    count_edges<<<(E + 255) / 256, 256>>>(ei, et, E);
    invert_cnt<<<(NNODES * RREL + 255) / 256, 256>>>();

    const int initBlocks = (NNODES * (KDIM / 4) + 255) / 256;
    const int scatBlocks = (E * 32 + 255) / 256;

    // ---- layer 1 ----
    init_H<false><<<initBlocks, 256>>>(x);
    scatter_edges<false><<<scatBlocks, 256>>>(ei, et, x, E);
    dim3 g1((NNODES + 127) / 128, HIDD / 128);
    gemm_k<HIDD, true, true><<<g1, 256>>>(bias1, nullptr);

    // ---- layer 2 ----
    init_H<true><<<initBlocks, 256>>>(nullptr);
    scatter_edges<true><<<scatBlocks, 256>>>(ei, et, nullptr, E);
    dim3 g2((NNODES + 127) / 128, ZDIM / 128);
    gemm_k<ZDIM, false, false><<<g2, 256>>>(bias2, out);
}

// round 6
// speedup vs baseline: 1.4700x; 1.4700x over previous
#include <cuda_runtime.h>
#include <cuda_bf16.h>
#include <cstdint>

#define NNODES 30000
#define RREL   8
#define DIM    256
#define KDIM   2304          // R*DIM + DIM
#define HIDD   256
#define ZDIM   128
#define NBASE  30
#define BK     32            // K per chunk
#define NCH    (KDIM / BK)   // 72
#define STRB   80            // smem row stride bytes (40 bf16, conflict-free ldmatrix)
#define BUFB   (128 * STRB)  // 10240 B per matrix buffer
#define STAGEB (4 * BUFB)    // Ah, Al, Bh, Bl
#define SMEMB  (2 * STAGEB)  // 81920 B double-buffered

// ---- static device scratch ----
__device__ float g_H[(size_t)NNODES * KDIM];
__device__ float g_Z[(size_t)NNODES * HIDD];
__device__ float g_cnt[NNODES * RREL];
__device__ __align__(16) __nv_bfloat16 g_W1h[(size_t)HIDD * KDIM];
__device__ __align__(16) __nv_bfloat16 g_W1l[(size_t)HIDD * KDIM];
__device__ __align__(16) __nv_bfloat16 g_W2h[(size_t)ZDIM * KDIM];
__device__ __align__(16) __nv_bfloat16 g_W2l[(size_t)ZDIM * KDIM];

// ---------------------------------------------------------------------------
__device__ __forceinline__ uint32_t smem_u32(const void* p) {
    uint32_t a;
    asm("{ .reg .u64 t; cvta.to.shared.u64 t, %1; cvt.u32.u64 %0, t; }"
        : "=r"(a) : "l"(p));
    return a;
}
#define CP_ASYNC16(dst, src) \
    asm volatile("cp.async.cg.shared.global [%0], [%1], 16;" :: "r"(dst), "l"(src))
#define CP_COMMIT() asm volatile("cp.async.commit_group;" ::: "memory")
#define CP_WAIT0()  asm volatile("cp.async.wait_group 0;" ::: "memory")

__device__ __forceinline__ void ldsm4(uint32_t& r0, uint32_t& r1, uint32_t& r2,
                                      uint32_t& r3, uint32_t a) {
    asm volatile("ldmatrix.sync.aligned.m8n8.x4.shared.b16 {%0,%1,%2,%3}, [%4];"
                 : "=r"(r0), "=r"(r1), "=r"(r2), "=r"(r3) : "r"(a));
}
__device__ __forceinline__ void mma16816(float* c, const uint32_t* a,
                                         const uint32_t* b) {
    asm volatile(
        "mma.sync.aligned.m16n8k16.row.col.f32.bf16.bf16.f32 "
        "{%0,%1,%2,%3}, {%4,%5,%6,%7}, {%8,%9}, {%0,%1,%2,%3};"
        : "+f"(c[0]), "+f"(c[1]), "+f"(c[2]), "+f"(c[3])
        : "r"(a[0]), "r"(a[1]), "r"(a[2]), "r"(a[3]), "r"(b[0]), "r"(b[1]));
}

// ---------------------------------------------------------------------------
// Build transposed split weights: Wt[o][k] = hi/lo bf16 of W[k][o]
// ---------------------------------------------------------------------------
template<int OUTD, bool L1SEL>
__global__ void build_wt(const float* __restrict__ bases,
                         const float* __restrict__ comp,
                         const float* __restrict__ root)
{
    __nv_bfloat16* __restrict__ Wh = L1SEL ? g_W1h : g_W2h;
    __nv_bfloat16* __restrict__ Wl = L1SEL ? g_W1l : g_W2l;
    int idx = blockIdx.x * blockDim.x + threadIdx.x;
    if (idx >= KDIM * OUTD) return;
    int k = idx / OUTD;
    int o = idx - k * OUTD;
    float w;
    if (k < RREL * DIM) {
        int r = k >> 8, i = k & 255;
        w = 0.f;
        #pragma unroll
        for (int b = 0; b < NBASE; b++)
            w += comp[r * NBASE + b] * bases[((size_t)b * DIM + i) * OUTD + o];
    } else {
        w = root[(size_t)(k - RREL * DIM) * OUTD + o];
    }
    __nv_bfloat16 h = __float2bfloat16(w);
    __nv_bfloat16 l = __float2bfloat16(w - __bfloat162float(h));
    Wh[(size_t)o * KDIM + k] = h;
    Wl[(size_t)o * KDIM + k] = l;
}

// ---------------------------------------------------------------------------
// Counts / init / scatter (unchanged from R4-passing version)
// ---------------------------------------------------------------------------
__global__ void zero_cnt_kernel()
{
    int i = blockIdx.x * blockDim.x + threadIdx.x;
    if (i < NNODES * RREL) g_cnt[i] = 0.f;
}

__global__ void count_edges(const int* __restrict__ ei,
                            const int* __restrict__ et, int E)
{
    int e = blockIdx.x * blockDim.x + threadIdx.x;
    if (e >= E) return;
    int dst = ei[E + e];
    int r   = et[e];
    if ((unsigned)dst >= NNODES || (unsigned)r >= RREL) return;
    atomicAdd(&g_cnt[dst * RREL + r], 1.0f);
}

__global__ void invert_cnt()
{
    int i = blockIdx.x * blockDim.x + threadIdx.x;
    if (i < NNODES * RREL) g_cnt[i] = 1.0f / fmaxf(g_cnt[i], 1.0f);
}

template<bool USE_GZ>
__global__ void init_H(const float* __restrict__ tail)
{
    const int per = KDIM / 4;
    int idx = blockIdx.x * blockDim.x + threadIdx.x;
    if (idx >= NNODES * per) return;
    int n = idx / per;
    int c = idx - n * per;
    float4 v;
    if (c < (RREL * DIM) / 4) {
        v = make_float4(0.f, 0.f, 0.f, 0.f);
    } else {
        const float4* t4 = USE_GZ ? (const float4*)g_Z : (const float4*)tail;
        v = t4[(size_t)n * (DIM / 4) + (c - (RREL * DIM) / 4)];
    }
    ((float4*)g_H)[idx] = v;
}

template<bool USE_GZ>
__global__ void scatter_edges(const int* __restrict__ ei,
                              const int* __restrict__ et,
                              const float* __restrict__ feat_in, int E)
{
    int gw   = (blockIdx.x * blockDim.x + threadIdx.x) >> 5;
    int lane = threadIdx.x & 31;
    if (gw >= E) return;
    const float* __restrict__ feat = USE_GZ ? g_Z : feat_in;
    int src = ei[gw];
    int dst = ei[E + gw];
    int r   = et[gw];
    if ((unsigned)src >= NNODES || (unsigned)dst >= NNODES ||
        (unsigned)r >= RREL) return;
    float s = g_cnt[dst * RREL + r];
    const float4* xr = (const float4*)(feat + (size_t)src * DIM);
    float* hb = g_H + (size_t)dst * KDIM + r * DIM;
    #pragma unroll
    for (int i = 0; i < 2; i++) {
        int f = lane + 32 * i;
        float4 v = xr[f];
        float* p = hb + 4 * f;
        atomicAdd(p + 0, v.x * s);
        atomicAdd(p + 1, v.y * s);
        atomicAdd(p + 2, v.z * s);
        atomicAdd(p + 3, v.w * s);
    }
}

// ---------------------------------------------------------------------------
// bf16-split mma.sync GEMM: C[M,OUTD] = g_H[M,2304] @ Wt^T + bias (leaky opt.)
// CTA tile 128x128, 8 warps (4x2), warp tile 32x64, k-chunk 32, double buffer.
// Per stage smem: Ah | Al | Bh | Bl, each 128 rows x 80B (padded, SW-free).
// ---------------------------------------------------------------------------
template<int OUTD, bool RELU, bool TO_GZ>
__global__ void __launch_bounds__(256, 2)
gemm_mma(const float* __restrict__ bias, float* __restrict__ Cout)
{
    extern __shared__ char smc[];
    const uint32_t smb = smem_u32(smc);
    const int tid  = threadIdx.x;
    const int lane = tid & 31, wid = tid >> 5;
    const int wm = wid & 3, wn = wid >> 2;
    const int bm = blockIdx.x * 128, bn = blockIdx.y * 128;
    const __nv_bfloat16* __restrict__ Wh = (OUTD == HIDD) ? g_W1h : g_W2h;
    const __nv_bfloat16* __restrict__ Wl = (OUTD == HIDD) ? g_W1l : g_W2l;
    float* __restrict__ C = TO_GZ ? g_Z : Cout;

    const int lrow  = tid >> 1;     // 0..127
    const int lhalf = tid & 1;      // k-subtile of 16
    const bool arowok = (bm + lrow) < NNODES;
    const float* agp = g_H + (size_t)(bm + lrow) * KDIM + lhalf * 16;
    const __nv_bfloat16* bgh = Wh + (size_t)(bn + lrow) * KDIM + lhalf * 16;
    const __nv_bfloat16* bgl = Wl + (size_t)(bn + lrow) * KDIM + lhalf * 16;
    const uint32_t arowoff = (uint32_t)(lrow * STRB + lhalf * 32);

    float acc[2][8][4];
    #pragma unroll
    for (int i = 0; i < 2; i++)
        #pragma unroll
        for (int j = 0; j < 8; j++)
            #pragma unroll
            for (int q = 0; q < 4; q++) acc[i][j][q] = 0.f;

    float4 ar[4];

    auto ldgA = [&](int c) {
        if (arowok) {
            const float4* p = (const float4*)(agp + c * BK);
            ar[0] = p[0]; ar[1] = p[1]; ar[2] = p[2]; ar[3] = p[3];
        } else {
            ar[0] = ar[1] = ar[2] = ar[3] = make_float4(0.f, 0.f, 0.f, 0.f);
        }
    };
    auto stsA = [&](int s) {
        union { __nv_bfloat16 b[16]; uint4 u[2]; } Hb, Lb;
        const float* f = (const float*)ar;
        #pragma unroll
        for (int i = 0; i < 16; i++) {
            __nv_bfloat16 h = __float2bfloat16(f[i]);
            Hb.b[i] = h;
            Lb.b[i] = __float2bfloat16(f[i] - __bfloat162float(h));
        }
        char* p = smc + s * STAGEB + lrow * STRB + lhalf * 32;
        *(uint4*)(p)             = Hb.u[0];
        *(uint4*)(p + 16)        = Hb.u[1];
        *(uint4*)(p + BUFB)      = Lb.u[0];
        *(uint4*)(p + BUFB + 16) = Lb.u[1];
    };
    auto cpB = [&](int c, int s) {
        uint32_t dst = smb + s * STAGEB + 2 * BUFB + arowoff;
        const char* sh = (const char*)(bgh + c * BK);
        const char* sl = (const char*)(bgl + c * BK);
        CP_ASYNC16(dst, sh);
        CP_ASYNC16(dst + 16, sh + 16);
        CP_ASYNC16(dst + BUFB, sl);
        CP_ASYNC16(dst + BUFB + 16, sl + 16);
    };
    auto comp = [&](int s) {
        uint32_t abase = smb + s * STAGEB;
        uint32_t bbase = abase + 2 * BUFB;
        #pragma unroll
        for (int ks = 0; ks < 2; ks++) {
            uint32_t ah[2][4], al[2][4];
            #pragma unroll
            for (int mt = 0; mt < 2; mt++) {
                int row = wm * 32 + mt * 16 + (lane & 15);
                uint32_t ad = abase + row * STRB + ks * 32 + ((lane >> 4) << 4);
                ldsm4(ah[mt][0], ah[mt][1], ah[mt][2], ah[mt][3], ad);
                ldsm4(al[mt][0], al[mt][1], al[mt][2], al[mt][3], ad + BUFB);
            }
            #pragma unroll
            for (int nq = 0; nq < 4; nq++) {
                int row = wn * 64 + nq * 16 + (lane & 15);
                uint32_t bd = bbase + row * STRB + ks * 32 + ((lane >> 4) << 4);
                uint32_t bh[4], bl[4];
                ldsm4(bh[0], bh[1], bh[2], bh[3], bd);
                ldsm4(bl[0], bl[1], bl[2], bl[3], bd + BUFB);
                #pragma unroll
                for (int half = 0; half < 2; half++) {
                    int nf = nq * 2 + half;
                    uint32_t bhp[2] = { bh[half], bh[half + 2] };
                    uint32_t blp[2] = { bl[half], bl[half + 2] };
                    #pragma unroll
                    for (int mt = 0; mt < 2; mt++) {
                        mma16816(acc[mt][nf], ah[mt], bhp);
                        mma16816(acc[mt][nf], ah[mt], blp);
                        mma16816(acc[mt][nf], al[mt], bhp);
                    }
                }
            }
        }
    };

    // prologue: stage 0
    ldgA(0);
    cpB(0, 0);
    CP_COMMIT();
    stsA(0);
    CP_WAIT0();
    __syncthreads();

    #pragma unroll 1
    for (int c = 0; c < NCH; c++) {
        int s = c & 1;
        if (c + 1 < NCH) {
            ldgA(c + 1);           // LDG in flight across comp
            cpB(c + 1, s ^ 1);
            CP_COMMIT();
        }
        comp(s);
        if (c + 1 < NCH) {
            stsA(s ^ 1);
            CP_WAIT0();
        }
        __syncthreads();
    }

    // epilogue
    float bv[8][2];
    #pragma unroll
    for (int nf = 0; nf < 8; nf++) {
        int col = bn + wn * 64 + nf * 8 + (lane & 3) * 2;
        bv[nf][0] = bias[col];
        bv[nf][1] = bias[col + 1];
    }
    #pragma unroll
    for (int mt = 0; mt < 2; mt++) {
        int r0 = bm + wm * 32 + mt * 16 + (lane >> 2);
        #pragma unroll
        for (int rh = 0; rh < 2; rh++) {
            int rr = r0 + rh * 8;
            if (rr < NNODES) {
                #pragma unroll
                for (int nf = 0; nf < 8; nf++) {
                    int col = bn + wn * 64 + nf * 8 + (lane & 3) * 2;
                    float vx = acc[mt][nf][rh * 2 + 0] + bv[nf][0];
                    float vy = acc[mt][nf][rh * 2 + 1] + bv[nf][1];
                    if (RELU) {
                        vx = vx > 0.f ? vx : 0.01f * vx;
                        vy = vy > 0.f ? vy : 0.01f * vy;
                    }
                    *(float2*)(C + (size_t)rr * OUTD + col) = make_float2(vx, vy);
                }
            }
        }
    }
}

// ---------------------------------------------------------------------------
extern "C" void kernel_launch(void* const* d_in, const int* in_sizes, int n_in,
                              void* d_out, int out_size)
{
    const float* x      = (const float*)d_in[0];
    const int*   ei     = (const int*)d_in[1];
    const int*   et     = (const int*)d_in[2];
    const float* bases1 = (const float*)d_in[3];
    const float* comp1  = (const float*)d_in[4];
    const float* root1  = (const float*)d_in[5];
    const float* bias1  = (const float*)d_in[6];
    const float* bases2 = (const float*)d_in[7];
    const float* comp2  = (const float*)d_in[8];
    const float* root2  = (const float*)d_in[9];
    const float* bias2  = (const float*)d_in[10];
    float* out = (float*)d_out;
    int E = in_sizes[2];

    cudaFuncSetAttribute(gemm_mma<HIDD, true, true>,
                         cudaFuncAttributeMaxDynamicSharedMemorySize, SMEMB);
    cudaFuncSetAttribute(gemm_mma<ZDIM, false, false>,
                         cudaFuncAttributeMaxDynamicSharedMemorySize, SMEMB);

    build_wt<HIDD, true ><<<(KDIM * HIDD + 255) / 256, 256>>>(bases1, comp1, root1);
    build_wt<ZDIM, false><<<(KDIM * ZDIM + 255) / 256, 256>>>(bases2, comp2, root2);

    zero_cnt_kernel<<<(NNODES * RREL + 255) / 256, 256>>>();
    count_edges<<<(E + 255) / 256, 256>>>(ei, et, E);
    invert_cnt<<<(NNODES * RREL + 255) / 256, 256>>>();

    const int initBlocks = (NNODES * (KDIM / 4) + 255) / 256;
    const int scatBlocks = (E * 32 + 255) / 256;
    const int mtiles = (NNODES + 127) / 128;   // 235

    // ---- layer 1 ----
    init_H<false><<<initBlocks, 256>>>(x);
    scatter_edges<false><<<scatBlocks, 256>>>(ei, et, x, E);
    gemm_mma<HIDD, true, true><<<dim3(mtiles, HIDD / 128), 256, SMEMB>>>(bias1, nullptr);

    // ---- layer 2 ----
    init_H<true><<<initBlocks, 256>>>(nullptr);
    scatter_edges<true><<<scatBlocks, 256>>>(ei, et, nullptr, E);
    gemm_mma<ZDIM, false, false><<<dim3(mtiles, ZDIM / 128), 256, SMEMB>>>(bias2, out);
}

// round 8
// speedup vs baseline: 1.8651x; 1.2688x over previous
#include <cuda_runtime.h>
#include <cuda_bf16.h>
#include <cstdint>

#define NNODES 30000
#define RREL   8
#define DIM    256
#define KDIM   2304          // R*DIM + DIM
#define HIDD   256
#define ZDIM   128
#define NBASE  30
#define BK     32            // K per chunk
#define NCH    (KDIM / BK)   // 72
#define STRB   80            // smem row stride bytes
#define ABUF   (128 * STRB)  // 10240 B per A matrix buffer

// ---- static device scratch ----
__device__ float g_H[(size_t)NNODES * KDIM];
__device__ float g_Z[(size_t)NNODES * HIDD];
__device__ float g_cnt[NNODES * RREL];
__device__ __align__(16) __nv_bfloat16 g_W1h[(size_t)HIDD * KDIM];
__device__ __align__(16) __nv_bfloat16 g_W1l[(size_t)HIDD * KDIM];
__device__ __align__(16) __nv_bfloat16 g_W2h[(size_t)ZDIM * KDIM];
__device__ __align__(16) __nv_bfloat16 g_W2l[(size_t)ZDIM * KDIM];

// ---------------------------------------------------------------------------
__device__ __forceinline__ uint32_t smem_u32(const void* p) {
    uint32_t a;
    asm("{ .reg .u64 t; cvta.to.shared.u64 t, %1; cvt.u32.u64 %0, t; }"
        : "=r"(a) : "l"(p));
    return a;
}
#define CP_ASYNC16(dst, src) \
    asm volatile("cp.async.cg.shared.global [%0], [%1], 16;" :: "r"(dst), "l"(src))
#define CP_COMMIT() asm volatile("cp.async.commit_group;" ::: "memory")
#define CP_WAIT0()  asm volatile("cp.async.wait_group 0;" ::: "memory")

__device__ __forceinline__ void ldsm4(uint32_t& r0, uint32_t& r1, uint32_t& r2,
                                      uint32_t& r3, uint32_t a) {
    asm volatile("ldmatrix.sync.aligned.m8n8.x4.shared.b16 {%0,%1,%2,%3}, [%4];"
                 : "=r"(r0), "=r"(r1), "=r"(r2), "=r"(r3) : "r"(a));
}
__device__ __forceinline__ void mma16816(float* c, const uint32_t* a,
                                         const uint32_t* b) {
    asm volatile(
        "mma.sync.aligned.m16n8k16.row.col.f32.bf16.bf16.f32 "
        "{%0,%1,%2,%3}, {%4,%5,%6,%7}, {%8,%9}, {%0,%1,%2,%3};"
        : "+f"(c[0]), "+f"(c[1]), "+f"(c[2]), "+f"(c[3])
        : "r"(a[0]), "r"(a[1]), "r"(a[2]), "r"(a[3]), "r"(b[0]), "r"(b[1]));
}

// ---------------------------------------------------------------------------
// Build transposed split weights: Wt[o][k] = hi/lo bf16 of W[k][o]
// ---------------------------------------------------------------------------
template<int OUTD, bool L1SEL>
__global__ void build_wt(const float* __restrict__ bases,
                         const float* __restrict__ comp,
                         const float* __restrict__ root)
{
    __nv_bfloat16* __restrict__ Wh = L1SEL ? g_W1h : g_W2h;
    __nv_bfloat16* __restrict__ Wl = L1SEL ? g_W1l : g_W2l;
    int idx = blockIdx.x * blockDim.x + threadIdx.x;
    if (idx >= KDIM * OUTD) return;
    int k = idx / OUTD;
    int o = idx - k * OUTD;
    float w;
    if (k < RREL * DIM) {
        int r = k >> 8, i = k & 255;
        w = 0.f;
        #pragma unroll
        for (int b = 0; b < NBASE; b++)
            w += comp[r * NBASE + b] * bases[((size_t)b * DIM + i) * OUTD + o];
    } else {
        w = root[(size_t)(k - RREL * DIM) * OUTD + o];
    }
    __nv_bfloat16 h = __float2bfloat16(w);
    __nv_bfloat16 l = __float2bfloat16(w - __bfloat162float(h));
    Wh[(size_t)o * KDIM + k] = h;
    Wl[(size_t)o * KDIM + k] = l;
}

// ---------------------------------------------------------------------------
// Counts / init
// ---------------------------------------------------------------------------
__global__ void zero_cnt_kernel()
{
    int i = blockIdx.x * blockDim.x + threadIdx.x;
    if (i < NNODES * RREL) g_cnt[i] = 0.f;
}

__global__ void count_edges(const int* __restrict__ ei,
                            const int* __restrict__ et, int E)
{
    int e = blockIdx.x * blockDim.x + threadIdx.x;
    if (e >= E) return;
    int dst = ei[E + e];
    int r   = et[e];
    if ((unsigned)dst >= NNODES || (unsigned)r >= RREL) return;
    atomicAdd(&g_cnt[dst * RREL + r], 1.0f);
}

__global__ void invert_cnt()
{
    int i = blockIdx.x * blockDim.x + threadIdx.x;
    if (i < NNODES * RREL) g_cnt[i] = 1.0f / fmaxf(g_cnt[i], 1.0f);
}

template<bool USE_GZ>
__global__ void init_H(const float* __restrict__ tail)
{
    const int per = KDIM / 4;
    int idx = blockIdx.x * blockDim.x + threadIdx.x;
    if (idx >= NNODES * per) return;
    int n = idx / per;
    int c = idx - n * per;
    float4 v;
    if (c < (RREL * DIM) / 4) {
        v = make_float4(0.f, 0.f, 0.f, 0.f);
    } else {
        const float4* t4 = USE_GZ ? (const float4*)g_Z : (const float4*)tail;
        v = t4[(size_t)n * (DIM / 4) + (c - (RREL * DIM) / 4)];
    }
    ((float4*)g_H)[idx] = v;
}

// ---------------------------------------------------------------------------
// Scatter: 64 threads per edge, one vector red.v4.f32 (16B) per thread.
// DIM=256 floats = 64 float4s per edge.
// ---------------------------------------------------------------------------
template<bool USE_GZ>
__global__ void scatter_edges(const int* __restrict__ ei,
                              const int* __restrict__ et,
                              const float* __restrict__ feat_in, int E)
{
    int t = blockIdx.x * blockDim.x + threadIdx.x;
    int e = t >> 6, j = t & 63;
    if (e >= E) return;
    const float* __restrict__ feat = USE_GZ ? g_Z : feat_in;
    int src = ei[e];
    int dst = ei[E + e];
    int r   = et[e];
    if ((unsigned)src >= NNODES || (unsigned)dst >= NNODES ||
        (unsigned)r >= RREL) return;
    float s = g_cnt[dst * RREL + r];
    float4 v = ((const float4*)(feat + (size_t)src * DIM))[j];
    float* p = g_H + (size_t)dst * KDIM + r * DIM + 4 * j;
    asm volatile("red.global.add.v4.f32 [%0], {%1,%2,%3,%4};"
                 :: "l"(p), "f"(v.x * s), "f"(v.y * s), "f"(v.z * s), "f"(v.w * s)
                 : "memory");
}

// ---------------------------------------------------------------------------
// bf16-split mma.sync GEMM: C[M,OUTD] = g_H[M,2304] @ Wt^T + bias (leaky opt.)
// CTA tile 128 x OUTD (N-full), THREADS = 2*OUTD, warp grid 4 x (OUTD/64),
// warp tile 32x64, k-chunk 32, double-buffered smem.
// Per stage: Ah(10240) Al(10240) Bh(OUTD*80) Bl(OUTD*80).
// ---------------------------------------------------------------------------
template<int OUTD, bool RELU, bool TO_GZ>
__global__ void __launch_bounds__(2 * OUTD, 1)
gemm_mma(const float* __restrict__ bias, float* __restrict__ Cout)
{
    constexpr int THREADS = 2 * OUTD;
    constexpr int BBUF = OUTD * STRB;
    constexpr int STAGEB = 2 * ABUF + 2 * BBUF;
    constexpr int TPR_A = THREADS / 128;     // threads per A row (4 or 2)
    constexpr int FLTS  = BK / TPR_A;        // floats per thread (8 or 16)

    extern __shared__ char smc[];
    const uint32_t smb = smem_u32(smc);
    const int tid  = threadIdx.x;
    const int lane = tid & 31, wid = tid >> 5;
    const int wm = wid & 3, wn = wid >> 2;
    const int bm = blockIdx.x * 128;
    const __nv_bfloat16* __restrict__ Wh = (OUTD == HIDD) ? g_W1h : g_W2h;
    const __nv_bfloat16* __restrict__ Wl = (OUTD == HIDD) ? g_W1l : g_W2l;
    float* __restrict__ C = TO_GZ ? g_Z : Cout;

    // A loader coords
    const int arow = tid / TPR_A;            // 0..127
    const int asub = tid % TPR_A;            // k-subchunk
    const bool arowok = (bm + arow) < NNODES;
    const float* agp = g_H + (size_t)(bm + arow) * KDIM + asub * FLTS;
    // B loader coords (2 threads per row, 32B each)
    const int brow  = tid >> 1;              // 0..OUTD-1
    const int bhalf = tid & 1;
    const __nv_bfloat16* bgh = Wh + (size_t)brow * KDIM + bhalf * 16;
    const __nv_bfloat16* bgl = Wl + (size_t)brow * KDIM + bhalf * 16;
    const uint32_t browoff = (uint32_t)(brow * STRB + bhalf * 32);

    float acc[2][8][4];
    #pragma unroll
    for (int i = 0; i < 2; i++)
        #pragma unroll
        for (int j = 0; j < 8; j++)
            #pragma unroll
            for (int q = 0; q < 4; q++) acc[i][j][q] = 0.f;

    float4 ar[FLTS / 4];

    auto ldgA = [&](int c) {
        if (arowok) {
            const float4* p = (const float4*)(agp + c * BK);
            #pragma unroll
            for (int i = 0; i < FLTS / 4; i++) ar[i] = p[i];
        } else {
            #pragma unroll
            for (int i = 0; i < FLTS / 4; i++)
                ar[i] = make_float4(0.f, 0.f, 0.f, 0.f);
        }
    };
    auto stsA = [&](int s) {
        union { __nv_bfloat16 b[FLTS]; uint4 u[FLTS / 8]; } Hb, Lb;
        const float* f = (const float*)ar;
        #pragma unroll
        for (int i = 0; i < FLTS; i++) {
            __nv_bfloat16 h = __float2bfloat16(f[i]);
            Hb.b[i] = h;
            Lb.b[i] = __float2bfloat16(f[i] - __bfloat162float(h));
        }
        char* p = smc + s * STAGEB + arow * STRB + asub * (FLTS * 2);
        #pragma unroll
        for (int i = 0; i < FLTS / 8; i++) {
            *(uint4*)(p + 16 * i)        = Hb.u[i];
            *(uint4*)(p + ABUF + 16 * i) = Lb.u[i];
        }
    };
    auto cpB = [&](int c, int s) {
        uint32_t dst = smb + s * STAGEB + 2 * ABUF + browoff;
        const char* sh = (const char*)(bgh + c * BK);
        const char* sl = (const char*)(bgl + c * BK);
        CP_ASYNC16(dst, sh);
        CP_ASYNC16(dst + 16, sh + 16);
        CP_ASYNC16(dst + BBUF, sl);
        CP_ASYNC16(dst + BBUF + 16, sl + 16);
    };
    auto comp = [&](int s) {
        uint32_t abase = smb + s * STAGEB;
        uint32_t bbase = abase + 2 * ABUF;
        #pragma unroll
        for (int ks = 0; ks < 2; ks++) {
            uint32_t ah[2][4], al[2][4];
            #pragma unroll
            for (int mt = 0; mt < 2; mt++) {
                int row = wm * 32 + mt * 16 + (lane & 15);
                uint32_t ad = abase + row * STRB + ks * 32 + ((lane >> 4) << 4);
                ldsm4(ah[mt][0], ah[mt][1], ah[mt][2], ah[mt][3], ad);
                ldsm4(al[mt][0], al[mt][1], al[mt][2], al[mt][3], ad + ABUF);
            }
            #pragma unroll
            for (int nq = 0; nq < 4; nq++) {
                int row = wn * 64 + nq * 16 + (lane & 15);
                uint32_t bd = bbase + row * STRB + ks * 32 + ((lane >> 4) << 4);
                uint32_t bh[4], bl[4];
                ldsm4(bh[0], bh[1], bh[2], bh[3], bd);
                ldsm4(bl[0], bl[1], bl[2], bl[3], bd + BBUF);
                #pragma unroll
                for (int half = 0; half < 2; half++) {
                    int nf = nq * 2 + half;
                    uint32_t bhp[2] = { bh[half], bh[half + 2] };
                    uint32_t blp[2] = { bl[half], bl[half + 2] };
                    #pragma unroll
                    for (int mt = 0; mt < 2; mt++) {
                        mma16816(acc[mt][nf], ah[mt], bhp);
                        mma16816(acc[mt][nf], ah[mt], blp);
                        mma16816(acc[mt][nf], al[mt], bhp);
                    }
                }
            }
        }
    };

    // prologue
    ldgA(0);
    cpB(0, 0);
    CP_COMMIT();
    stsA(0);
    CP_WAIT0();
    __syncthreads();

    #pragma unroll 1
    for (int c = 0; c < NCH; c++) {
        int s = c & 1;
        if (c + 1 < NCH) {
            ldgA(c + 1);
            cpB(c + 1, s ^ 1);
            CP_COMMIT();
        }
        comp(s);
        if (c + 1 < NCH) {
            stsA(s ^ 1);
            CP_WAIT0();
        }
        __syncthreads();
    }

    // epilogue
    float bv[8][2];
    #pragma unroll
    for (int nf = 0; nf < 8; nf++) {
        int col = wn * 64 + nf * 8 + (lane & 3) * 2;
        bv[nf][0] = bias[col];
        bv[nf][1] = bias[col + 1];
    }
    #pragma unroll
    for (int mt = 0; mt < 2; mt++) {
        int r0 = bm + wm * 32 + mt * 16 + (lane >> 2);
        #pragma unroll
        for (int rh = 0; rh < 2; rh++) {
            int rr = r0 + rh * 8;
            if (rr < NNODES) {
                #pragma unroll
                for (int nf = 0; nf < 8; nf++) {
                    int col = wn * 64 + nf * 8 + (lane & 3) * 2;
                    float vx = acc[mt][nf][rh * 2 + 0] + bv[nf][0];
                    float vy = acc[mt][nf][rh * 2 + 1] + bv[nf][1];
                    if (RELU) {
                        vx = vx > 0.f ? vx : 0.01f * vx;
                        vy = vy > 0.f ? vy : 0.01f * vy;
                    }
                    *(float2*)(C + (size_t)rr * OUTD + col) = make_float2(vx, vy);
                }
            }
        }
    }
}

// ---------------------------------------------------------------------------
extern "C" void kernel_launch(void* const* d_in, const int* in_sizes, int n_in,
                              void* d_out, int out_size)
{
    const float* x      = (const float*)d_in[0];
    const int*   ei     = (const int*)d_in[1];
    const int*   et     = (const int*)d_in[2];
    const float* bases1 = (const float*)d_in[3];
    const float* comp1  = (const float*)d_in[4];
    const float* root1  = (const float*)d_in[5];
    const float* bias1  = (const float*)d_in[6];
    const float* bases2 = (const float*)d_in[7];
    const float* comp2  = (const float*)d_in[8];
    const float* root2  = (const float*)d_in[9];
    const float* bias2  = (const float*)d_in[10];
    float* out = (float*)d_out;
    int E = in_sizes[2];

    constexpr int SM1 = 2 * (2 * ABUF + 2 * HIDD * STRB);   // 122880
    constexpr int SM2 = 2 * (2 * ABUF + 2 * ZDIM * STRB);   // 81920
    cudaFuncSetAttribute(gemm_mma<HIDD, true, true>,
                         cudaFuncAttributeMaxDynamicSharedMemorySize, SM1);
    cudaFuncSetAttribute(gemm_mma<ZDIM, false, false>,
                         cudaFuncAttributeMaxDynamicSharedMemorySize, SM2);

    build_wt<HIDD, true ><<<(KDIM * HIDD + 255) / 256, 256>>>(bases1, comp1, root1);
    build_wt<ZDIM, false><<<(KDIM * ZDIM + 255) / 256, 256>>>(bases2, comp2, root2);

    zero_cnt_kernel<<<(NNODES * RREL + 255) / 256, 256>>>();
    count_edges<<<(E + 255) / 256, 256>>>(ei, et, E);
    invert_cnt<<<(NNODES * RREL + 255) / 256, 256>>>();

    const int initBlocks = (NNODES * (KDIM / 4) + 255) / 256;
    const int scatBlocks = (E * 64 + 255) / 256;     // 64 threads per edge
    const int mtiles = (NNODES + 127) / 128;         // 235

    // ---- layer 1 ----
    init_H<false><<<initBlocks, 256>>>(x);
    scatter_edges<false><<<scatBlocks, 256>>>(ei, et, x, E);
    gemm_mma<HIDD, true, true><<<mtiles, 2 * HIDD, SM1>>>(bias1, nullptr);

    // ---- layer 2 ----
    init_H<true><<<initBlocks, 256>>>(nullptr);
    scatter_edges<true><<<scatBlocks, 256>>>(ei, et, nullptr, E);
    gemm_mma<ZDIM, false, false><<<mtiles, 2 * ZDIM, SM2>>>(bias2, out);
}

// round 9
// speedup vs baseline: 2.0975x; 1.1246x over previous
#include <cuda_runtime.h>
#include <cuda_bf16.h>
#include <cstdint>

#define NNODES 30000
#define NPAD   30080         // 235 * 128, padded M for unguarded A loads
#define RREL   8
#define DIM    256
#define KDIM   2304          // R*DIM + DIM
#define HIDD   256
#define ZDIM   128
#define NBASE  30
#define BK     32            // K per chunk
#define NCH    (KDIM / BK)   // 72
#define STRB   80            // smem row stride bytes
#define ABUF   (128 * STRB)  // 10240 B per A matrix buffer
#define NSEG   (NNODES * RREL)   // 240000
#define EMAX   480000
#define SCB    512
#define NSCB   ((NSEG + SCB - 1) / SCB)  // 469

// ---- static device scratch ----
__device__ float g_Z[(size_t)NNODES * HIDD];
__device__ __align__(16) __nv_bfloat16 g_Hh[(size_t)NPAD * KDIM];  // A hi (pad rows stay 0)
__device__ __align__(16) __nv_bfloat16 g_Hl[(size_t)NPAD * KDIM];  // A lo
__device__ __align__(16) __nv_bfloat16 g_W1h[(size_t)HIDD * KDIM];
__device__ __align__(16) __nv_bfloat16 g_W1l[(size_t)HIDD * KDIM];
__device__ __align__(16) __nv_bfloat16 g_W2h[(size_t)ZDIM * KDIM];
__device__ __align__(16) __nv_bfloat16 g_W2l[(size_t)ZDIM * KDIM];
__device__ int g_cnt[NSEG];
__device__ int g_off[NSEG];
__device__ int g_cur[NSEG];
__device__ int g_bsum[NSCB];
__device__ int g_esrc[EMAX];

// ---------------------------------------------------------------------------
__device__ __forceinline__ uint32_t smem_u32(const void* p) {
    uint32_t a;
    asm("{ .reg .u64 t; cvta.to.shared.u64 t, %1; cvt.u32.u64 %0, t; }"
        : "=r"(a) : "l"(p));
    return a;
}
#define CP_ASYNC16(dst, src) \
    asm volatile("cp.async.cg.shared.global [%0], [%1], 16;" :: "r"(dst), "l"(src))
#define CP_COMMIT() asm volatile("cp.async.commit_group;" ::: "memory")
#define CP_WAIT0()  asm volatile("cp.async.wait_group 0;" ::: "memory")

__device__ __forceinline__ void ldsm4(uint32_t& r0, uint32_t& r1, uint32_t& r2,
                                      uint32_t& r3, uint32_t a) {
    asm volatile("ldmatrix.sync.aligned.m8n8.x4.shared.b16 {%0,%1,%2,%3}, [%4];"
                 : "=r"(r0), "=r"(r1), "=r"(r2), "=r"(r3) : "r"(a));
}
__device__ __forceinline__ void mma16816(float* c, const uint32_t* a,
                                         const uint32_t* b) {
    asm volatile(
        "mma.sync.aligned.m16n8k16.row.col.f32.bf16.bf16.f32 "
        "{%0,%1,%2,%3}, {%4,%5,%6,%7}, {%8,%9}, {%0,%1,%2,%3};"
        : "+f"(c[0]), "+f"(c[1]), "+f"(c[2]), "+f"(c[3])
        : "r"(a[0]), "r"(a[1]), "r"(a[2]), "r"(a[3]), "r"(b[0]), "r"(b[1]));
}

// ---------------------------------------------------------------------------
// Build transposed split weights: Wt[o][k] = hi/lo bf16 of W[k][o]
// ---------------------------------------------------------------------------
template<int OUTD, bool L1SEL>
__global__ void build_wt(const float* __restrict__ bases,
                         const float* __restrict__ comp,
                         const float* __restrict__ root)
{
    __nv_bfloat16* __restrict__ Wh = L1SEL ? g_W1h : g_W2h;
    __nv_bfloat16* __restrict__ Wl = L1SEL ? g_W1l : g_W2l;
    int idx = blockIdx.x * blockDim.x + threadIdx.x;
    if (idx >= KDIM * OUTD) return;
    int k = idx / OUTD;
    int o = idx - k * OUTD;
    float w;
    if (k < RREL * DIM) {
        int r = k >> 8, i = k & 255;
        w = 0.f;
        #pragma unroll
        for (int b = 0; b < NBASE; b++)
            w += comp[r * NBASE + b] * bases[((size_t)b * DIM + i) * OUTD + o];
    } else {
        w = root[(size_t)(k - RREL * DIM) * OUTD + o];
    }
    __nv_bfloat16 h = __float2bfloat16(w);
    __nv_bfloat16 l = __float2bfloat16(w - __bfloat162float(h));
    Wh[(size_t)o * KDIM + k] = h;
    Wl[(size_t)o * KDIM + k] = l;
}

// ---------------------------------------------------------------------------
// CSR build: count -> exclusive scan (3 kernels) -> fill (src per slot)
// ---------------------------------------------------------------------------
__global__ void zero_csr()
{
    int i = blockIdx.x * blockDim.x + threadIdx.x;
    if (i < NSEG) { g_cnt[i] = 0; g_cur[i] = 0; }
}

__global__ void count_edges(const int* __restrict__ ei,
                            const int* __restrict__ et, int E)
{
    int e = blockIdx.x * blockDim.x + threadIdx.x;
    if (e >= E) return;
    int dst = ei[E + e];
    int r   = et[e];
    if ((unsigned)dst >= NNODES || (unsigned)r >= RREL) return;
    atomicAdd(&g_cnt[dst * RREL + r], 1);
}

__global__ void scan1()
{
    __shared__ int sh[SCB];
    int i = blockIdx.x * SCB + threadIdx.x;
    int v = (i < NSEG) ? g_cnt[i] : 0;
    sh[threadIdx.x] = v;
    __syncthreads();
    #pragma unroll
    for (int d = 1; d < SCB; d <<= 1) {
        int t = (threadIdx.x >= d) ? sh[threadIdx.x - d] : 0;
        __syncthreads();
        sh[threadIdx.x] += t;
        __syncthreads();
    }
    if (i < NSEG) g_off[i] = sh[threadIdx.x] - v;     // exclusive
    if (threadIdx.x == SCB - 1) g_bsum[blockIdx.x] = sh[SCB - 1];
}

__global__ void scan2()
{
    __shared__ int sh[SCB];
    int v = (threadIdx.x < NSCB) ? g_bsum[threadIdx.x] : 0;
    sh[threadIdx.x] = v;
    __syncthreads();
    #pragma unroll
    for (int d = 1; d < SCB; d <<= 1) {
        int t = (threadIdx.x >= d) ? sh[threadIdx.x - d] : 0;
        __syncthreads();
        sh[threadIdx.x] += t;
        __syncthreads();
    }
    if (threadIdx.x < NSCB) g_bsum[threadIdx.x] = sh[threadIdx.x] - v;
}

__global__ void scan3()
{
    int i = blockIdx.x * SCB + threadIdx.x;
    if (i < NSEG) g_off[i] += g_bsum[blockIdx.x];
}

__global__ void fill_csr(const int* __restrict__ ei,
                         const int* __restrict__ et, int E)
{
    int e = blockIdx.x * blockDim.x + threadIdx.x;
    if (e >= E) return;
    int src = ei[e];
    int dst = ei[E + e];
    int r   = et[e];
    if ((unsigned)src >= NNODES || (unsigned)dst >= NNODES ||
        (unsigned)r >= RREL) return;
    int seg = dst * RREL + r;
    int pos = g_off[seg] + atomicAdd(&g_cur[seg], 1);
    g_esrc[pos] = src;
}

// ---------------------------------------------------------------------------
// Aggregate: one warp per (dst, r) segment -> mean of x[src] rows, written as
// bf16 hi/lo directly into g_Hh/g_Hl (zeros for empty segments). Warps past
// NSEG copy the self-feature tail block.
// ---------------------------------------------------------------------------
template<bool USE_GZ>
__global__ void aggregate(const float* __restrict__ feat_in)
{
    int w    = (blockIdx.x * blockDim.x + threadIdx.x) >> 5;
    int lane = threadIdx.x & 31;
    if (w >= NSEG + NNODES) return;
    const float* __restrict__ feat = USE_GZ ? g_Z : feat_in;

    float4 a0 = make_float4(0.f, 0.f, 0.f, 0.f);
    float4 a1 = make_float4(0.f, 0.f, 0.f, 0.f);
    size_t base;

    if (w < NSEG) {
        int n = g_cnt[w], off = g_off[w];
        for (int i = 0; i < n; i++) {
            int src = g_esrc[off + i];
            const float4* xr = (const float4*)(feat + (size_t)src * DIM);
            float4 v0 = xr[lane], v1 = xr[lane + 32];
            a0.x += v0.x; a0.y += v0.y; a0.z += v0.z; a0.w += v0.w;
            a1.x += v1.x; a1.y += v1.y; a1.z += v1.z; a1.w += v1.w;
        }
        if (n > 1) {
            float s = 1.f / n;
            a0.x *= s; a0.y *= s; a0.z *= s; a0.w *= s;
            a1.x *= s; a1.y *= s; a1.z *= s; a1.w *= s;
        }
        int dst = w >> 3, r = w & 7;
        base = (size_t)dst * KDIM + r * DIM;
    } else {
        int node = w - NSEG;
        const float4* xr = (const float4*)(feat + (size_t)node * DIM);
        a0 = xr[lane]; a1 = xr[lane + 32];
        base = (size_t)node * KDIM + RREL * DIM;
    }

    union { __nv_bfloat16 b[4]; uint2 u; } h0, l0, h1, l1;
    const float* f0 = (const float*)&a0;
    const float* f1 = (const float*)&a1;
    #pragma unroll
    for (int i = 0; i < 4; i++) {
        __nv_bfloat16 h = __float2bfloat16(f0[i]);
        h0.b[i] = h; l0.b[i] = __float2bfloat16(f0[i] - __bfloat162float(h));
        h = __float2bfloat16(f1[i]);
        h1.b[i] = h; l1.b[i] = __float2bfloat16(f1[i] - __bfloat162float(h));
    }
    *(uint2*)(g_Hh + base + lane * 4)       = h0.u;
    *(uint2*)(g_Hh + base + 128 + lane * 4) = h1.u;
    *(uint2*)(g_Hl + base + lane * 4)       = l0.u;
    *(uint2*)(g_Hl + base + 128 + lane * 4) = l1.u;
}

// ---------------------------------------------------------------------------
// bf16-split mma.sync GEMM: C[M,OUTD] = H[M,2304] @ Wt^T + bias (leaky opt.)
// A and B both bf16 hi/lo in global, pure cp.async double-buffered pipeline.
// CTA tile 128 x OUTD, THREADS = 2*OUTD, warp tile 32x64, k-chunk 32.
// Per stage: Ah(10240) Al(10240) Bh(OUTD*80) Bl(OUTD*80).
// ---------------------------------------------------------------------------
template<int OUTD, bool RELU, bool TO_GZ>
__global__ void __launch_bounds__(2 * OUTD, 1)
gemm_mma(const float* __restrict__ bias, float* __restrict__ Cout)
{
    constexpr int THREADS = 2 * OUTD;
    constexpr int BBUF = OUTD * STRB;
    constexpr int STAGEB = 2 * ABUF + 2 * BBUF;
    constexpr int TPR_A = THREADS / 128;     // threads per A row (4 or 2)
    constexpr int BPT_A = 64 / TPR_A;        // bytes per thread per buffer (16/32)

    extern __shared__ char smc[];
    const uint32_t smb = smem_u32(smc);
    const int tid  = threadIdx.x;
    const int lane = tid & 31, wid = tid >> 5;
    const int wm = wid & 3, wn = wid >> 2;
    const int bm = blockIdx.x * 128;
    const __nv_bfloat16* __restrict__ Wh = (OUTD == HIDD) ? g_W1h : g_W2h;
    const __nv_bfloat16* __restrict__ Wl = (OUTD == HIDD) ? g_W1l : g_W2l;
    float* __restrict__ C = TO_GZ ? g_Z : Cout;

    // A loader coords (rows padded to NPAD -> no bounds check)
    const int arow = tid / TPR_A;
    const int asub = tid % TPR_A;
    const __nv_bfloat16* agh = g_Hh + (size_t)(bm + arow) * KDIM + asub * (BPT_A / 2);
    const __nv_bfloat16* agl = g_Hl + (size_t)(bm + arow) * KDIM + asub * (BPT_A / 2);
    const uint32_t arowoff = (uint32_t)(arow * STRB + asub * BPT_A);
    // B loader coords (2 threads per row, 32B each)
    const int brow  = tid >> 1;
    const int bhalf = tid & 1;
    const __nv_bfloat16* bgh = Wh + (size_t)brow * KDIM + bhalf * 16;
    const __nv_bfloat16* bgl = Wl + (size_t)brow * KDIM + bhalf * 16;
    const uint32_t browoff = (uint32_t)(brow * STRB + bhalf * 32);

    float acc[2][8][4];
    #pragma unroll
    for (int i = 0; i < 2; i++)
        #pragma unroll
        for (int j = 0; j < 8; j++)
            #pragma unroll
            for (int q = 0; q < 4; q++) acc[i][j][q] = 0.f;

    auto cpA = [&](int c, int s) {
        uint32_t dst = smb + s * STAGEB + arowoff;
        const char* sh = (const char*)(agh + c * BK);
        const char* sl = (const char*)(agl + c * BK);
        #pragma unroll
        for (int i = 0; i < BPT_A / 16; i++) {
            CP_ASYNC16(dst + 16 * i, sh + 16 * i);
            CP_ASYNC16(dst + ABUF + 16 * i, sl + 16 * i);
        }
    };
    auto cpB = [&](int c, int s) {
        uint32_t dst = smb + s * STAGEB + 2 * ABUF + browoff;
        const char* sh = (const char*)(bgh + c * BK);
        const char* sl = (const char*)(bgl + c * BK);
        CP_ASYNC16(dst, sh);
        CP_ASYNC16(dst + 16, sh + 16);
        CP_ASYNC16(dst + BBUF, sl);
        CP_ASYNC16(dst + BBUF + 16, sl + 16);
    };
    auto comp = [&](int s) {
        uint32_t abase = smb + s * STAGEB;
        uint32_t bbase = abase + 2 * ABUF;
        #pragma unroll
        for (int ks = 0; ks < 2; ks++) {
            uint32_t ah[2][4], al[2][4];
            #pragma unroll
            for (int mt = 0; mt < 2; mt++) {
                int row = wm * 32 + mt * 16 + (lane & 15);
                uint32_t ad = abase + row * STRB + ks * 32 + ((lane >> 4) << 4);
                ldsm4(ah[mt][0], ah[mt][1], ah[mt][2], ah[mt][3], ad);
                ldsm4(al[mt][0], al[mt][1], al[mt][2], al[mt][3], ad + ABUF);
            }
            #pragma unroll
            for (int nq = 0; nq < 4; nq++) {
                int row = wn * 64 + nq * 16 + (lane & 15);
                uint32_t bd = bbase + row * STRB + ks * 32 + ((lane >> 4) << 4);
                uint32_t bh[4], bl[4];
                ldsm4(bh[0], bh[1], bh[2], bh[3], bd);
                ldsm4(bl[0], bl[1], bl[2], bl[3], bd + BBUF);
                #pragma unroll
                for (int half = 0; half < 2; half++) {
                    int nf = nq * 2 + half;
                    uint32_t bhp[2] = { bh[half], bh[half + 2] };
                    uint32_t blp[2] = { bl[half], bl[half + 2] };
                    #pragma unroll
                    for (int mt = 0; mt < 2; mt++) {
                        mma16816(acc[mt][nf], ah[mt], bhp);
                        mma16816(acc[mt][nf], ah[mt], blp);
                        mma16816(acc[mt][nf], al[mt], bhp);
                    }
                }
            }
        }
    };

    // prologue
    cpA(0, 0);
    cpB(0, 0);
    CP_COMMIT();
    CP_WAIT0();
    __syncthreads();

    #pragma unroll 1
    for (int c = 0; c < NCH; c++) {
        int s = c & 1;
        if (c + 1 < NCH) {
            cpA(c + 1, s ^ 1);
            cpB(c + 1, s ^ 1);
            CP_COMMIT();
        }
        comp(s);
        if (c + 1 < NCH) CP_WAIT0();
        __syncthreads();
    }

    // epilogue
    float bv[8][2];
    #pragma unroll
    for (int nf = 0; nf < 8; nf++) {
        int col = wn * 64 + nf * 8 + (lane & 3) * 2;
        bv[nf][0] = bias[col];
        bv[nf][1] = bias[col + 1];
    }
    #pragma unroll
    for (int mt = 0; mt < 2; mt++) {
        int r0 = bm + wm * 32 + mt * 16 + (lane >> 2);
        #pragma unroll
        for (int rh = 0; rh < 2; rh++) {
            int rr = r0 + rh * 8;
            if (rr < NNODES) {
                #pragma unroll
                for (int nf = 0; nf < 8; nf++) {
                    int col = wn * 64 + nf * 8 + (lane & 3) * 2;
                    float vx = acc[mt][nf][rh * 2 + 0] + bv[nf][0];
                    float vy = acc[mt][nf][rh * 2 + 1] + bv[nf][1];
                    if (RELU) {
                        vx = vx > 0.f ? vx : 0.01f * vx;
                        vy = vy > 0.f ? vy : 0.01f * vy;
                    }
                    *(float2*)(C + (size_t)rr * OUTD + col) = make_float2(vx, vy);
                }
            }
        }
    }
}

// ---------------------------------------------------------------------------
extern "C" void kernel_launch(void* const* d_in, const int* in_sizes, int n_in,
                              void* d_out, int out_size)
{
    const float* x      = (const float*)d_in[0];
    const int*   ei     = (const int*)d_in[1];
    const int*   et     = (const int*)d_in[2];
    const float* bases1 = (const float*)d_in[3];
    const float* comp1  = (const float*)d_in[4];
    const float* root1  = (const float*)d_in[5];
    const float* bias1  = (const float*)d_in[6];
    const float* bases2 = (const float*)d_in[7];
    const float* comp2  = (const float*)d_in[8];
    const float* root2  = (const float*)d_in[9];
    const float* bias2  = (const float*)d_in[10];
    float* out = (float*)d_out;
    int E = in_sizes[2];

    constexpr int SM1 = 2 * (2 * ABUF + 2 * HIDD * STRB);   // 122880
    constexpr int SM2 = 2 * (2 * ABUF + 2 * ZDIM * STRB);   // 81920
    cudaFuncSetAttribute(gemm_mma<HIDD, true, true>,
                         cudaFuncAttributeMaxDynamicSharedMemorySize, SM1);
    cudaFuncSetAttribute(gemm_mma<ZDIM, false, false>,
                         cudaFuncAttributeMaxDynamicSharedMemorySize, SM2);

    build_wt<HIDD, true ><<<(KDIM * HIDD + 255) / 256, 256>>>(bases1, comp1, root1);
    build_wt<ZDIM, false><<<(KDIM * ZDIM + 255) / 256, 256>>>(bases2, comp2, root2);

    // CSR (built once, shared by both layers)
    zero_csr<<<(NSEG + 255) / 256, 256>>>();
    count_edges<<<(E + 255) / 256, 256>>>(ei, et, E);
    scan1<<<NSCB, SCB>>>();
    scan2<<<1, SCB>>>();
    scan3<<<NSCB, SCB>>>();
    fill_csr<<<(E + 255) / 256, 256>>>(ei, et, E);

    const int aggBlocks = ((NSEG + NNODES) * 32 + 255) / 256;
    const int mtiles = (NNODES + 127) / 128;   // 235

    // ---- layer 1 ----
    aggregate<false><<<aggBlocks, 256>>>(x);
    gemm_mma<HIDD, true, true><<<mtiles, 2 * HIDD, SM1>>>(bias1, nullptr);

    // ---- layer 2 ----
    aggregate<true><<<aggBlocks, 256>>>(nullptr);
    gemm_mma<ZDIM, false, false><<<mtiles, 2 * ZDIM, SM2>>>(bias2, out);
}

// round 11
// speedup vs baseline: 2.8815x; 1.3738x over previous
#include <cuda_runtime.h>
#include <cuda_fp16.h>
#include <cstdint>

#define NNODES 30000
#define NPAD   30080         // 235 * 128, padded M for unguarded A loads
#define RREL   8
#define DIM    256
#define KDIM   2304          // R*DIM + DIM
#define HIDD   256
#define ZDIM   128
#define NBASE  30
#define BK     32            // K per chunk
#define NCH    (KDIM / BK)   // 72
#define STRB   80            // smem row stride bytes
#define ABUF   (128 * STRB)  // 10240 B for A (single fp16 buffer)
#define NSEG   (NNODES * RREL)   // 240000
#define EMAX   480000
#define SCB    512
#define NSCB   ((NSEG + SCB - 1) / SCB)  // 469

// ---- static device scratch ----
__device__ float g_Z[(size_t)NNODES * HIDD];
__device__ __align__(16) __half g_Ha[(size_t)NPAD * KDIM];   // A fp16 (pad rows 0)
__device__ __align__(16) __half g_W1h[(size_t)HIDD * KDIM];
__device__ __align__(16) __half g_W1l[(size_t)HIDD * KDIM];
__device__ __align__(16) __half g_W2h[(size_t)ZDIM * KDIM];
__device__ __align__(16) __half g_W2l[(size_t)ZDIM * KDIM];
__device__ int g_cnt[NSEG];
__device__ int g_off[NSEG];
__device__ int g_cur[NSEG];
__device__ int g_bsum[NSCB];
__device__ int g_esrc[EMAX];

// ---------------------------------------------------------------------------
__device__ __forceinline__ uint32_t smem_u32(const void* p) {
    uint32_t a;
    asm("{ .reg .u64 t; cvta.to.shared.u64 t, %1; cvt.u32.u64 %0, t; }"
        : "=r"(a) : "l"(p));
    return a;
}
#define CP_ASYNC16(dst, src) \
    asm volatile("cp.async.cg.shared.global [%0], [%1], 16;" :: "r"(dst), "l"(src))
#define CP_COMMIT() asm volatile("cp.async.commit_group;" ::: "memory")
#define CP_WAIT0()  asm volatile("cp.async.wait_group 0;" ::: "memory")

__device__ __forceinline__ void ldsm4(uint32_t& r0, uint32_t& r1, uint32_t& r2,
                                      uint32_t& r3, uint32_t a) {
    asm volatile("ldmatrix.sync.aligned.m8n8.x4.shared.b16 {%0,%1,%2,%3}, [%4];"
                 : "=r"(r0), "=r"(r1), "=r"(r2), "=r"(r3) : "r"(a));
}
__device__ __forceinline__ void mma16816(float* c, const uint32_t* a,
                                         const uint32_t* b) {
    asm volatile(
        "mma.sync.aligned.m16n8k16.row.col.f32.f16.f16.f32 "
        "{%0,%1,%2,%3}, {%4,%5,%6,%7}, {%8,%9}, {%0,%1,%2,%3};"
        : "+f"(c[0]), "+f"(c[1]), "+f"(c[2]), "+f"(c[3])
        : "r"(a[0]), "r"(a[1]), "r"(a[2]), "r"(a[3]), "r"(b[0]), "r"(b[1]));
}

// ---------------------------------------------------------------------------
// Build transposed split weights: Wt[o][k] = hi/lo fp16 of W[k][o]
// ---------------------------------------------------------------------------
template<int OUTD, bool L1SEL>
__global__ void build_wt(const float* __restrict__ bases,
                         const float* __restrict__ comp,
                         const float* __restrict__ root)
{
    __half* __restrict__ Wh = L1SEL ? g_W1h : g_W2h;
    __half* __restrict__ Wl = L1SEL ? g_W1l : g_W2l;
    int idx = blockIdx.x * blockDim.x + threadIdx.x;
    if (idx >= KDIM * OUTD) return;
    int k = idx / OUTD;
    int o = idx - k * OUTD;
    float w;
    if (k < RREL * DIM) {
        int r = k >> 8, i = k & 255;
        w = 0.f;
        #pragma unroll
        for (int b = 0; b < NBASE; b++)
            w += comp[r * NBASE + b] * bases[((size_t)b * DIM + i) * OUTD + o];
    } else {
        w = root[(size_t)(k - RREL * DIM) * OUTD + o];
    }
    __half h = __float2half_rn(w);
    __half l = __float2half_rn(w - __half2float(h));
    Wh[(size_t)o * KDIM + k] = h;
    Wl[(size_t)o * KDIM + k] = l;
}

// ---------------------------------------------------------------------------
// CSR build: count -> exclusive scan (3 kernels) -> fill (src per slot)
// ---------------------------------------------------------------------------
__global__ void zero_csr()
{
    int i = blockIdx.x * blockDim.x + threadIdx.x;
    if (i < NSEG) { g_cnt[i] = 0; g_cur[i] = 0; }
}

__global__ void count_edges(const int* __restrict__ ei,
                            const int* __restrict__ et, int E)
{
    int e = blockIdx.x * blockDim.x + threadIdx.x;
    if (e >= E) return;
    int dst = ei[E + e];
    int r   = et[e];
    if ((unsigned)dst >= NNODES || (unsigned)r >= RREL) return;
    atomicAdd(&g_cnt[dst * RREL + r], 1);
}

__global__ void scan1()
{
    __shared__ int sh[SCB];
    int i = blockIdx.x * SCB + threadIdx.x;
    int v = (i < NSEG) ? g_cnt[i] : 0;
    sh[threadIdx.x] = v;
    __syncthreads();
    #pragma unroll
    for (int d = 1; d < SCB; d <<= 1) {
        int t = (threadIdx.x >= d) ? sh[threadIdx.x - d] : 0;
        __syncthreads();
        sh[threadIdx.x] += t;
        __syncthreads();
    }
    if (i < NSEG) g_off[i] = sh[threadIdx.x] - v;     // exclusive
    if (threadIdx.x == SCB - 1) g_bsum[blockIdx.x] = sh[SCB - 1];
}

__global__ void scan2()
{
    __shared__ int sh[SCB];
    int v = (threadIdx.x < NSCB) ? g_bsum[threadIdx.x] : 0;
    sh[threadIdx.x] = v;
    __syncthreads();
    #pragma unroll
    for (int d = 1; d < SCB; d <<= 1) {
        int t = (threadIdx.x >= d) ? sh[threadIdx.x - d] : 0;
        __syncthreads();
        sh[threadIdx.x] += t;
        __syncthreads();
    }
    if (threadIdx.x < NSCB) g_bsum[threadIdx.x] = sh[threadIdx.x] - v;
}

__global__ void scan3()
{
    int i = blockIdx.x * SCB + threadIdx.x;
    if (i < NSEG) g_off[i] += g_bsum[blockIdx.x];
}

__global__ void fill_csr(const int* __restrict__ ei,
                         const int* __restrict__ et, int E)
{
    int e = blockIdx.x * blockDim.x + threadIdx.x;
    if (e >= E) return;
    int src = ei[e];
    int dst = ei[E + e];
    int r   = et[e];
    if ((unsigned)src >= NNODES || (unsigned)dst >= NNODES ||
        (unsigned)r >= RREL) return;
    int seg = dst * RREL + r;
    int pos = g_off[seg] + atomicAdd(&g_cur[seg], 1);
    g_esrc[pos] = src;
}

// ---------------------------------------------------------------------------
// Aggregate: one warp per (dst, r) segment -> mean of x[src] rows, written as
// fp16 directly into g_Ha (zeros for empty segments). Warps past NSEG copy the
// self-feature tail block.
// ---------------------------------------------------------------------------
template<bool USE_GZ>
__global__ void aggregate(const float* __restrict__ feat_in)
{
    int w    = (blockIdx.x * blockDim.x + threadIdx.x) >> 5;
    int lane = threadIdx.x & 31;
    if (w >= NSEG + NNODES) return;
    const float* __restrict__ feat = USE_GZ ? g_Z : feat_in;

    float4 a0 = make_float4(0.f, 0.f, 0.f, 0.f);
    float4 a1 = make_float4(0.f, 0.f, 0.f, 0.f);
    size_t base;

    if (w < NSEG) {
        int n = g_cnt[w], off = g_off[w];
        for (int i = 0; i < n; i++) {
            int src = g_esrc[off + i];
            const float4* xr = (const float4*)(feat + (size_t)src * DIM);
            float4 v0 = xr[lane], v1 = xr[lane + 32];
            a0.x += v0.x; a0.y += v0.y; a0.z += v0.z; a0.w += v0.w;
            a1.x += v1.x; a1.y += v1.y; a1.z += v1.z; a1.w += v1.w;
        }
        if (n > 1) {
            float s = 1.f / n;
            a0.x *= s; a0.y *= s; a0.z *= s; a0.w *= s;
            a1.x *= s; a1.y *= s; a1.z *= s; a1.w *= s;
        }
        int dst = w >> 3, r = w & 7;
        base = (size_t)dst * KDIM + r * DIM;
    } else {
        int node = w - NSEG;
        const float4* xr = (const float4*)(feat + (size_t)node * DIM);
        a0 = xr[lane]; a1 = xr[lane + 32];
        base = (size_t)node * KDIM + RREL * DIM;
    }

    union { __half b[4]; uint2 u; } h0, h1;
    const float* f0 = (const float*)&a0;
    const float* f1 = (const float*)&a1;
    #pragma unroll
    for (int i = 0; i < 4; i++) {
        h0.b[i] = __float2half_rn(f0[i]);
        h1.b[i] = __float2half_rn(f1[i]);
    }
    *(uint2*)(g_Ha + base + lane * 4)       = h0.u;
    *(uint2*)(g_Ha + base + 128 + lane * 4) = h1.u;
}

// ---------------------------------------------------------------------------
// fp16 2-product mma.sync GEMM: C = H @ (Wh + Wl)^T + bias (leaky opt.)
// A single fp16 in global, B hi/lo fp16; pure cp.async double-buffered.
// CTA tile 128 x OUTD, THREADS = 2*OUTD, warp tile 32x64, k-chunk 32.
// Per stage: A(10240) Bh(OUTD*80) Bl(OUTD*80).
// ---------------------------------------------------------------------------
template<int OUTD, bool RELU, bool TO_GZ>
__global__ void __launch_bounds__(2 * OUTD, 1)
gemm_mma(const float* __restrict__ bias, float* __restrict__ Cout)
{
    constexpr int THREADS = 2 * OUTD;
    constexpr int BBUF = OUTD * STRB;
    constexpr int STAGEB = ABUF + 2 * BBUF;
    constexpr int TPR_A = THREADS / 128;     // threads per A row (4 or 2)
    constexpr int BPT_A = 64 / TPR_A;        // bytes per thread (16 or 32)

    extern __shared__ char smc[];
    const uint32_t smb = smem_u32(smc);
    const int tid  = threadIdx.x;
    const int lane = tid & 31, wid = tid >> 5;
    const int wm = wid & 3, wn = wid >> 2;
    const int bm = blockIdx.x * 128;
    const __half* __restrict__ Wh = (OUTD == HIDD) ? g_W1h : g_W2h;
    const __half* __restrict__ Wl = (OUTD == HIDD) ? g_W1l : g_W2l;
    float* __restrict__ C = TO_GZ ? g_Z : Cout;

    // A loader coords (rows padded to NPAD -> no bounds check)
    const int arow = tid / TPR_A;
    const int asub = tid % TPR_A;
    const __half* aga = g_Ha + (size_t)(bm + arow) * KDIM + asub * (BPT_A / 2);
    const uint32_t arowoff = (uint32_t)(arow * STRB + asub * BPT_A);
    // B loader coords (2 threads per row, 32B each)
    const int brow  = tid >> 1;
    const int bhalf = tid & 1;
    const __half* bgh = Wh + (size_t)brow * KDIM + bhalf * 16;
    const __half* bgl = Wl + (size_t)brow * KDIM + bhalf * 16;
    const uint32_t browoff = (uint32_t)(brow * STRB + bhalf * 32);

    float acc[2][8][4];
    #pragma unroll
    for (int i = 0; i < 2; i++)
        #pragma unroll
        for (int j = 0; j < 8; j++)
            #pragma unroll
            for (int q = 0; q < 4; q++) acc[i][j][q] = 0.f;

    auto cpA = [&](int c, int s) {
        uint32_t dst = smb + s * STAGEB + arowoff;
        const char* sa = (const char*)(aga + c * BK);
        #pragma unroll
        for (int i = 0; i < BPT_A / 16; i++)
            CP_ASYNC16(dst + 16 * i, sa + 16 * i);
    };
    auto cpB = [&](int c, int s) {
        uint32_t dst = smb + s * STAGEB + ABUF + browoff;
        const char* sh = (const char*)(bgh + c * BK);
        const char* sl = (const char*)(bgl + c * BK);
        CP_ASYNC16(dst, sh);
        CP_ASYNC16(dst + 16, sh + 16);
        CP_ASYNC16(dst + BBUF, sl);
        CP_ASYNC16(dst + BBUF + 16, sl + 16);
    };
    auto comp = [&](int s) {
        uint32_t abase = smb + s * STAGEB;
        uint32_t bbase = abase + ABUF;
        #pragma unroll
        for (int ks = 0; ks < 2; ks++) {
            uint32_t ah[2][4];
            #pragma unroll
            for (int mt = 0; mt < 2; mt++) {
                int row = wm * 32 + mt * 16 + (lane & 15);
                uint32_t ad = abase + row * STRB + ks * 32 + ((lane >> 4) << 4);
                ldsm4(ah[mt][0], ah[mt][1], ah[mt][2], ah[mt][3], ad);
            }
            #pragma unroll
            for (int nq = 0; nq < 4; nq++) {
                int row = wn * 64 + nq * 16 + (lane & 15);
                uint32_t bd = bbase + row * STRB + ks * 32 + ((lane >> 4) << 4);
                uint32_t bh[4], bl[4];
                ldsm4(bh[0], bh[1], bh[2], bh[3], bd);
                ldsm4(bl[0], bl[1], bl[2], bl[3], bd + BBUF);
                #pragma unroll
                for (int half = 0; half < 2; half++) {
                    int nf = nq * 2 + half;
                    uint32_t bhp[2] = { bh[half], bh[half + 2] };
                    uint32_t blp[2] = { bl[half], bl[half + 2] };
                    #pragma unroll
                    for (int mt = 0; mt < 2; mt++) {
                        mma16816(acc[mt][nf], ah[mt], bhp);
                        mma16816(acc[mt][nf], ah[mt], blp);
                    }
                }
            }
        }
    };

    // prologue
    cpA(0, 0);
    cpB(0, 0);
    CP_COMMIT();
    CP_WAIT0();
    __syncthreads();

    #pragma unroll 1
    for (int c = 0; c < NCH; c++) {
        int s = c & 1;
        if (c + 1 < NCH) {
            cpA(c + 1, s ^ 1);
            cpB(c + 1, s ^ 1);
            CP_COMMIT();
        }
        comp(s);
        if (c + 1 < NCH) CP_WAIT0();
        __syncthreads();
    }

    // epilogue
    float bv[8][2];
    #pragma unroll
    for (int nf = 0; nf < 8; nf++) {
        int col = wn * 64 + nf * 8 + (lane & 3) * 2;
        bv[nf][0] = bias[col];
        bv[nf][1] = bias[col + 1];
    }
    #pragma unroll
    for (int mt = 0; mt < 2; mt++) {
        int r0 = bm + wm * 32 + mt * 16 + (lane >> 2);
        #pragma unroll
        for (int rh = 0; rh < 2; rh++) {
            int rr = r0 + rh * 8;
            if (rr < NNODES) {
                #pragma unroll
                for (int nf = 0; nf < 8; nf++) {
                    int col = wn * 64 + nf * 8 + (lane & 3) * 2;
                    float vx = acc[mt][nf][rh * 2 + 0] + bv[nf][0];
                    float vy = acc[mt][nf][rh * 2 + 1] + bv[nf][1];
                    if (RELU) {
                        vx = vx > 0.f ? vx : 0.01f * vx;
                        vy = vy > 0.f ? vy : 0.01f * vy;
                    }
                    *(float2*)(C + (size_t)rr * OUTD + col) = make_float2(vx, vy);
                }
            }
        }
    }
}

// ---------------------------------------------------------------------------
extern "C" void kernel_launch(void* const* d_in, const int* in_sizes, int n_in,
                              void* d_out, int out_size)
{
    const float* x      = (const float*)d_in[0];
    const int*   ei     = (const int*)d_in[1];
    const int*   et     = (const int*)d_in[2];
    const float* bases1 = (const float*)d_in[3];
    const float* comp1  = (const float*)d_in[4];
    const float* root1  = (const float*)d_in[5];
    const float* bias1  = (const float*)d_in[6];
    const float* bases2 = (const float*)d_in[7];
    const float* comp2  = (const float*)d_in[8];
    const float* root2  = (const float*)d_in[9];
    const float* bias2  = (const float*)d_in[10];
    float* out = (float*)d_out;
    int E = in_sizes[2];

    constexpr int SM1 = 2 * (ABUF + 2 * HIDD * STRB);   // 102400
    constexpr int SM2 = 2 * (ABUF + 2 * ZDIM * STRB);   // 61440
    cudaFuncSetAttribute(gemm_mma<HIDD, true, true>,
                         cudaFuncAttributeMaxDynamicSharedMemorySize, SM1);
    cudaFuncSetAttribute(gemm_mma<ZDIM, false, false>,
                         cudaFuncAttributeMaxDynamicSharedMemorySize, SM2);

    build_wt<HIDD, true ><<<(KDIM * HIDD + 255) / 256, 256>>>(bases1, comp1, root1);
    build_wt<ZDIM, false><<<(KDIM * ZDIM + 255) / 256, 256>>>(bases2, comp2, root2);

    // CSR (built once, shared by both layers)
    zero_csr<<<(NSEG + 255) / 256, 256>>>();
    count_edges<<<(E + 255) / 256, 256>>>(ei, et, E);
    scan1<<<NSCB, SCB>>>();
    scan2<<<1, SCB>>>();
    scan3<<<NSCB, SCB>>>();
    fill_csr<<<(E + 255) / 256, 256>>>(ei, et, E);

    const int aggBlocks = ((NSEG + NNODES) * 32 + 255) / 256;
    const int mtiles = (NNODES + 127) / 128;   // 235

    // ---- layer 1 ----
    aggregate<false><<<aggBlocks, 256>>>(x);
    gemm_mma<HIDD, true, true><<<mtiles, 2 * HIDD, SM1>>>(bias1, nullptr);

    // ---- layer 2 ----
    aggregate<true><<<aggBlocks, 256>>>(nullptr);
    gemm_mma<ZDIM, false, false><<<mtiles, 2 * ZDIM, SM2>>>(bias2, out);
}